// round 13
// baseline (speedup 1.0000x reference)
#include <cuda_runtime.h>

#define NPTS 2048
#define KCAP 256
#define NTHREADS 256
#define ROWS_PER_BLOCK 2
#define WARPS_PER_ROW 4
#define CUT2 0.09f
#define EPSB 1e-3f
#define MWORDS 512    // 8 active-slot cells max * 64 words

#define MAX_OFFSET ((size_t)NPTS * KCAP * 4)

// Scratch (__device__ globals, allocation-free)
__device__ float4 g_sorted[NPTS];   // x-bucket-sorted points; .w = original j (bits)
__device__ int    g_bstart[257];    // bucket start offsets

// Single-block counting sort by x-bucket, 1024 threads (2 pts each).
__global__ __launch_bounds__(1024)
void pb_sort_kernel(const float* __restrict__ pos, float* __restrict__ out_max) {
    __shared__ int hist[256];
    __shared__ int cursor[256];
    __shared__ int wsum[8];
    const int tid = threadIdx.x;
    if (tid < 256) hist[tid] = 0;
    __syncthreads();

    float4 p[2]; int b[2];
#pragma unroll
    for (int rr = 0; rr < 2; rr++) {
        const int j = tid + rr * 1024;
        const float xx = pos[3 * j], yy = pos[3 * j + 1], zz = pos[3 * j + 2];
        int bb = (int)(xx * 256.0f);
        bb = bb < 0 ? 0 : (bb > 255 ? 255 : bb);
        p[rr] = make_float4(xx, yy, zz, __int_as_float(j));
        b[rr] = bb;
        atomicAdd(&hist[bb], 1);
    }
    __syncthreads();

    int incl = 0, v = 0;
    if (tid < 256) {
        const int lane = tid & 31;
        v = hist[tid];
        incl = v;
#pragma unroll
        for (int d = 1; d < 32; d <<= 1) {
            const int t = __shfl_up_sync(0xFFFFFFFFu, incl, d);
            if (lane >= d) incl += t;
        }
        if (lane == 31) wsum[tid >> 5] = incl;
    }
    __syncthreads();
    if (tid < 256) {
        const int w = tid >> 5;
        int woff = 0;
        for (int k = 0; k < w; k++) woff += wsum[k];
        const int excl = woff + incl - v;
        cursor[tid] = excl;
        g_bstart[tid] = excl;
        if (tid == 0) { g_bstart[256] = NPTS; *out_max = 0.0f; }
    }
    __syncthreads();

#pragma unroll
    for (int rr = 0; rr < 2; rr++) {
        const int dst = atomicAdd(&cursor[b[rr]], 1);
        g_sorted[dst] = p[rr];
    }
}

__global__ __launch_bounds__(NTHREADS, 7)
void pb_nbr_kernel(const float* __restrict__ pos, float* __restrict__ out) {
    __shared__ unsigned s_mask[ROWS_PER_BLOCK][MWORDS];           // 4 KB
    __shared__ unsigned short s_stage[ROWS_PER_BLOCK][KCAP];      // 1 KB
    __shared__ int s_wcnt[ROWS_PER_BLOCK][WARPS_PER_ROW];

    const int tid  = threadIdx.x;
    const int lane = tid & 31;
    const int w    = tid >> 5;
    const int r    = w >> 2;
    const int q    = w & 3;

    unsigned* mz = &s_mask[0][0];
    for (int k = tid; k < ROWS_PER_BLOCK * MWORDS; k += NTHREADS) mz[k] = 0u;
    __syncthreads();

    const int i = blockIdx.x * ROWS_PER_BLOCK + r;
    const float pix = __ldg(&pos[3 * i]);
    const float piy = __ldg(&pos[3 * i + 1]);
    const float piz = __ldg(&pos[3 * i + 2]);

    // Per-dim shift feasibility (margin 1e-4 >> fp32 rounding); -1/+1 mutually exclusive.
    const bool okxm = pix < 0.30001f, okxp = pix > 0.69999f;
    const bool okym = piy < 0.30001f, okyp = piy > 0.69999f;
    const bool okzm = piz < 0.30001f, okzp = piz > 0.69999f;

    const int nx = 1 + okxm + okxp, ny = 1 + okym + okyp, nz = 1 + okzm + okzp;
    const int nA = nx * ny * nz;
    const bool hy = okym || okyp;
    const bool hz = okzm || okzp;
    const float fy = okym ? -1.0f : 1.0f;
    const float fz = okzm ? -1.0f : 1.0f;

    // Ranks within ascending active lists -> slot = (posz*ny+posy)*nx+posx.
    const int posx1 = okxm ? 1 : 0;
    const int posy1 = okym ? 1 : 0;
    const int posz1 = okzm ? 1 : 0;
    const int posyS = okym ? 0 : 1;
    const int poszS = okzm ? 0 : 1;
    const int base00 = (posz1 * ny + posy1) * nx;
    const int baseY  = (posz1 * ny + posyS) * nx;
    const int baseZ  = (poszS * ny + posy1) * nx;
    const int baseYZ = (poszS * ny + posyS) * nx;

    // x bucket windows (conservative supersets)
    int blo0 = (int)floorf((pix - 0.3f - EPSB) * 256.0f); if (blo0 < 0) blo0 = 0;
    int bhi0 = (int)floorf((pix + 0.3f + EPSB) * 256.0f); if (bhi0 > 255) bhi0 = 255;
    int blo1 = (int)floorf((pix + 0.7f - EPSB) * 256.0f);
    if (blo1 > 255) blo1 = 255; if (blo1 < 0) blo1 = 0;
    int bhi2 = (int)floorf((pix - 0.7f + EPSB) * 256.0f);
    if (bhi2 > 255) bhi2 = 255; if (bhi2 < 0) bhi2 = 0;

    unsigned* __restrict__ rmask = s_mask[r];

    // ---- Discovery: order-free; hits -> flat slot bitmask via atomicOr ----
    // 2 candidates per lane per iteration; rare combos branch-skipped via ballot.
#pragma unroll
    for (int s = 0; s < 3; s++) {
        bool sval; float fsx; int posx, kb0, kb1; bool selfchk;
        if (s == 0)      { sval = true; fsx =  0.0f; posx = posx1;  kb0 = blo0; kb1 = bhi0; selfchk = true;  }
        else if (s == 1) { sval = okxm; fsx = -1.0f; posx = 0;      kb0 = blo1; kb1 = 255;  selfchk = false; }
        else             { sval = okxp; fsx =  1.0f; posx = nx - 1; kb0 = 0;    kb1 = bhi2; selfchk = false; }
        if (!sval) continue;
        unsigned* __restrict__ m00 = rmask + ((base00 + posx) << 6);
        unsigned* __restrict__ mY  = rmask + ((baseY  + posx) << 6);
        unsigned* __restrict__ mZ  = rmask + ((baseZ  + posx) << 6);
        unsigned* __restrict__ mYZ = rmask + ((baseYZ + posx) << 6);
        const int k0 = __ldg(&g_bstart[kb0]);
        const int k1 = __ldg(&g_bstart[kb1 + 1]);

        for (int base = k0 + q * 64; base < k1; base += WARPS_PER_ROW * 64) {
#pragma unroll
            for (int h = 0; h < 2; h++) {
                const int k = base + h * 32 + lane;
                const bool val = (k < k1);
                const float4 p = __ldg(&g_sorted[val ? k : k0]);
                const int jorig = __float_as_int(p.w);
                const int jw = jorig >> 5;
                const unsigned jb = 1u << (jorig & 31);
                // Exact reference rounding: ((p_j + s) - p_i), plain mul/add, no FMA.
                const float dx  = __fadd_rn(__fadd_rn(p.x, fsx), -pix);
                const float dx2 = __fmul_rn(dx, dx);
                const float dy0 = __fadd_rn(p.y, -piy);
                const float dz0 = __fadd_rn(p.z, -piz);
                const float dy0s = __fmul_rn(dy0, dy0);
                const float dz0s = __fmul_rn(dz0, dz0);
                {
                    const float d2 = __fadd_rn(__fadd_rn(dx2, dy0s), dz0s);
                    if (val && d2 <= CUT2 && !(selfchk && jorig == i))
                        atomicOr(&m00[jw], jb);
                }
                if (hy) {
                    const float dy1 = __fadd_rn(__fadd_rn(p.y, fy), -piy);
                    const float dy1s = __fmul_rn(dy1, dy1);
                    {
                        const float d2 = __fadd_rn(__fadd_rn(dx2, dy1s), dz0s);
                        const bool hitY = val && d2 <= CUT2;
                        if (__ballot_sync(0xFFFFFFFFu, hitY)) {
                            if (hitY) atomicOr(&mY[jw], jb);
                        }
                    }
                    if (hz) {
                        const float dz1 = __fadd_rn(__fadd_rn(p.z, fz), -piz);
                        const float dz1s = __fmul_rn(dz1, dz1);
                        const float d2 = __fadd_rn(__fadd_rn(dx2, dy1s), dz1s);
                        const bool hitYZ = val && d2 <= CUT2;
                        if (__ballot_sync(0xFFFFFFFFu, hitYZ)) {
                            if (hitYZ) atomicOr(&mYZ[jw], jb);
                        }
                    }
                }
                if (hz) {
                    const float dz1 = __fadd_rn(__fadd_rn(p.z, fz), -piz);
                    const float dz1s = __fmul_rn(dz1, dz1);
                    const float d2 = __fadd_rn(__fadd_rn(dx2, dy0s), dz1s);
                    const bool hitZ = val && d2 <= CUT2;
                    if (__ballot_sync(0xFFFFFFFFu, hitZ)) {
                        if (hitZ) atomicOr(&mZ[jw], jb);
                    }
                }
            }
        }
    }
    __syncthreads();

    // ---- Count: contiguous popc sweep over this warp's span ----
    const int myt0 = q * nA * 16;
    const int myt1 = myt0 + nA * 16;
    int cnt = 0;
    for (int t = myt0 + lane; t < myt1; t += 32) cnt += __popc(rmask[t]);
#pragma unroll
    for (int d = 16; d; d >>= 1) cnt += __shfl_xor_sync(0xFFFFFFFFu, cnt, d);
    if (lane == 0) s_wcnt[r][q] = cnt;
    __syncthreads();

    int base = 0, rowTotal = 0;
#pragma unroll
    for (int q2 = 0; q2 < WARPS_PER_ROW; q2++) {
        const int cc = s_wcnt[r][q2];
        if (q2 < q) base += cc;
        rowTotal += cc;
    }

    // ---- Emit phase 1: ordered bit expansion -> 16-bit codes in smem ----
    {
        unsigned short* __restrict__ rstage = s_stage[r];
        int off = base;
        int slot = 0;
        for (int zi = 0; zi < 3; zi++) {
            if ((zi == 0 && !okzm) || (zi == 2 && !okzp)) continue;
            for (int yi = 0; yi < 3; yi++) {
                if ((yi == 0 && !okym) || (yi == 2 && !okyp)) continue;
                for (int xi = 0; xi < 3; xi++) {
                    if ((xi == 0 && !okxm) || (xi == 2 && !okxp)) continue;
                    const int c = zi * 9 + yi * 3 + xi;     // canonical cell id
                    const int ccode = c << 11;
                    const int tb = slot << 6;
                    const int lo = myt0 > tb ? myt0 : tb;
                    const int hi = myt1 < tb + 64 ? myt1 : tb + 64;
                    for (int tg = lo; tg < hi; tg += 32) {
                        const int t = tg + lane;
                        unsigned word = (t < hi) ? rmask[t] : 0u;
                        const int pc = __popc(word);
                        int ex = pc;
#pragma unroll
                        for (int d = 1; d < 32; d <<= 1) {
                            const int tt = __shfl_up_sync(0xFFFFFFFFu, ex, d);
                            if (lane >= d) ex += tt;
                        }
                        int myoff = off + ex - pc;
                        const int jbase = (t - tb) << 5;
                        while (word) {
                            const int bit = __ffs(word) - 1;
                            word &= word - 1;
                            if (myoff < KCAP)
                                rstage[myoff] = (unsigned short)(ccode | (jbase + bit));
                            myoff++;
                        }
                        off += __shfl_sync(0xFFFFFFFFu, ex, 31);
                    }
                    slot++;
                }
            }
        }
    }
    __syncthreads();

    // ---- Emit phase 2: coalesced decode + fused tail fill ----
    float* __restrict__ out_neigh = out + (size_t)i * KCAP;
    float* __restrict__ out_cells = out + (size_t)NPTS * KCAP + (size_t)i * KCAP * 3;
    const unsigned short* __restrict__ rstage = s_stage[r];
    const int rowTid = tid & 127;
    const int filled = (rowTotal < KCAP) ? rowTotal : KCAP;
    for (int e = rowTid; e < KCAP; e += 128) {
        float vn, c0, c1, c2;
        if (e < filled) {
            const int code = rstage[e];
            const int j = code & 2047;
            const int c = code >> 11;
            vn = (float)j;
            c0 = (float)(c % 3 - 1);
            c1 = (float)((c / 3) % 3 - 1);
            c2 = (float)(c / 9 - 1);
        } else {
            vn = -1.0f; c0 = 1.0f; c1 = 1.0f; c2 = 1.0f;
        }
        out_neigh[e]         = vn;
        out_cells[3 * e]     = c0;
        out_cells[3 * e + 1] = c1;
        out_cells[3 * e + 2] = c2;
    }
    if (q == 0 && lane == 0) {
        atomicMax((int*)(out + MAX_OFFSET), __float_as_int((float)rowTotal));
    }
}

extern "C" void kernel_launch(void* const* d_in, const int* in_sizes, int n_in,
                              void* d_out, int out_size) {
    const float* pos = (const float*)d_in[0];
    float* out = (float*)d_out;
    pb_sort_kernel<<<1, 1024>>>(pos, out + MAX_OFFSET);
    pb_nbr_kernel<<<NPTS / ROWS_PER_BLOCK, NTHREADS>>>(pos, out);
}

// round 14
// speedup vs baseline: 1.0099x; 1.0099x over previous
#include <cuda_runtime.h>

#define NPTS 2048
#define KCAP 256
#define NTHREADS 128
#define WARPS_PER_ROW 4
#define CUT2 0.09f
#define EPSB 1e-3f
#define MWORDS 512    // 8 active-slot cells max * 64 words

#define MAX_OFFSET ((size_t)NPTS * KCAP * 4)

// Scratch (__device__ globals, allocation-free)
__device__ float4 g_sorted[NPTS];   // x-bucket-sorted points; .w = original j (bits)
__device__ int    g_bstart[257];    // bucket start offsets

// Single-block counting sort by x-bucket, 1024 threads (2 pts each).
__global__ __launch_bounds__(1024)
void pb_sort_kernel(const float* __restrict__ pos, float* __restrict__ out_max) {
    __shared__ int hist[256];
    __shared__ int cursor[256];
    __shared__ int wsum[8];
    const int tid = threadIdx.x;
    if (tid < 256) hist[tid] = 0;
    __syncthreads();

    float4 p[2]; int b[2];
#pragma unroll
    for (int rr = 0; rr < 2; rr++) {
        const int j = tid + rr * 1024;
        const float xx = pos[3 * j], yy = pos[3 * j + 1], zz = pos[3 * j + 2];
        int bb = (int)(xx * 256.0f);
        bb = bb < 0 ? 0 : (bb > 255 ? 255 : bb);
        p[rr] = make_float4(xx, yy, zz, __int_as_float(j));
        b[rr] = bb;
        atomicAdd(&hist[bb], 1);
    }
    __syncthreads();

    int incl = 0, v = 0;
    if (tid < 256) {
        const int lane = tid & 31;
        v = hist[tid];
        incl = v;
#pragma unroll
        for (int d = 1; d < 32; d <<= 1) {
            const int t = __shfl_up_sync(0xFFFFFFFFu, incl, d);
            if (lane >= d) incl += t;
        }
        if (lane == 31) wsum[tid >> 5] = incl;
    }
    __syncthreads();
    if (tid < 256) {
        const int w = tid >> 5;
        int woff = 0;
        for (int k = 0; k < w; k++) woff += wsum[k];
        const int excl = woff + incl - v;
        cursor[tid] = excl;
        g_bstart[tid] = excl;
        if (tid == 0) { g_bstart[256] = NPTS; *out_max = 0.0f; }
    }
    __syncthreads();

#pragma unroll
    for (int rr = 0; rr < 2; rr++) {
        const int dst = atomicAdd(&cursor[b[rr]], 1);
        g_sorted[dst] = p[rr];
    }
}

__global__ __launch_bounds__(NTHREADS, 16)
void pb_nbr_kernel(const float* __restrict__ pos, float* __restrict__ out) {
    __shared__ unsigned s_mask[MWORDS];           // 2 KB
    __shared__ unsigned short s_stage[KCAP];      // 0.5 KB
    __shared__ int s_wcnt[WARPS_PER_ROW];

    const int tid  = threadIdx.x;
    const int lane = tid & 31;
    const int q    = tid >> 5;   // warp within the row

    const int i = blockIdx.x;    // one row per block
    const float pix = __ldg(&pos[3 * i]);
    const float piy = __ldg(&pos[3 * i + 1]);
    const float piz = __ldg(&pos[3 * i + 2]);

    // Per-dim shift feasibility (margin 1e-4 >> fp32 rounding); -1/+1 mutually exclusive.
    const bool okxm = pix < 0.30001f, okxp = pix > 0.69999f;
    const bool okym = piy < 0.30001f, okyp = piy > 0.69999f;
    const bool okzm = piz < 0.30001f, okzp = piz > 0.69999f;

    const int nx = 1 + okxm + okxp, ny = 1 + okym + okyp, nz = 1 + okzm + okzp;
    const int nA = nx * ny * nz;
    const bool hy = okym || okyp;
    const bool hz = okzm || okzp;
    const float fy = okym ? -1.0f : 1.0f;
    const float fz = okzm ? -1.0f : 1.0f;

    // Zero only the active words
    for (int k = tid; k < nA * 64; k += NTHREADS) s_mask[k] = 0u;
    __syncthreads();

    // Ranks within ascending active lists -> slot = (posz*ny+posy)*nx+posx.
    const int posx1 = okxm ? 1 : 0;
    const int posy1 = okym ? 1 : 0;
    const int posz1 = okzm ? 1 : 0;
    const int posyS = okym ? 0 : 1;
    const int poszS = okzm ? 0 : 1;
    const int base00 = (posz1 * ny + posy1) * nx;
    const int baseY  = (posz1 * ny + posyS) * nx;
    const int baseZ  = (poszS * ny + posy1) * nx;
    const int baseYZ = (poszS * ny + posyS) * nx;

    // x bucket windows (conservative supersets)
    int blo0 = (int)floorf((pix - 0.3f - EPSB) * 256.0f); if (blo0 < 0) blo0 = 0;
    int bhi0 = (int)floorf((pix + 0.3f + EPSB) * 256.0f); if (bhi0 > 255) bhi0 = 255;
    int blo1 = (int)floorf((pix + 0.7f - EPSB) * 256.0f);
    if (blo1 > 255) blo1 = 255; if (blo1 < 0) blo1 = 0;
    int bhi2 = (int)floorf((pix - 0.7f + EPSB) * 256.0f);
    if (bhi2 > 255) bhi2 = 255; if (bhi2 < 0) bhi2 = 0;

    // ---- Discovery: order-free; hits -> flat slot bitmask via atomicOr ----
#pragma unroll
    for (int s = 0; s < 3; s++) {
        bool sval; float fsx; int posx, kb0, kb1; bool selfchk;
        if (s == 0)      { sval = true; fsx =  0.0f; posx = posx1;  kb0 = blo0; kb1 = bhi0; selfchk = true;  }
        else if (s == 1) { sval = okxm; fsx = -1.0f; posx = 0;      kb0 = blo1; kb1 = 255;  selfchk = false; }
        else             { sval = okxp; fsx =  1.0f; posx = nx - 1; kb0 = 0;    kb1 = bhi2; selfchk = false; }
        if (!sval) continue;
        unsigned* __restrict__ m00 = s_mask + ((base00 + posx) << 6);
        unsigned* __restrict__ mY  = s_mask + ((baseY  + posx) << 6);
        unsigned* __restrict__ mZ  = s_mask + ((baseZ  + posx) << 6);
        unsigned* __restrict__ mYZ = s_mask + ((baseYZ + posx) << 6);
        const int k0 = __ldg(&g_bstart[kb0]);
        const int k1 = __ldg(&g_bstart[kb1 + 1]);

        for (int base = k0 + q * 32; base < k1; base += WARPS_PER_ROW * 32) {
            const int k = base + lane;
            const bool val = (k < k1);
            const float4 p = __ldg(&g_sorted[val ? k : k0]);
            const int jorig = __float_as_int(p.w);
            const int jw = jorig >> 5;
            const unsigned jb = 1u << (jorig & 31);
            // Exact reference rounding: ((p_j + s) - p_i), plain mul/add, no FMA.
            const float dx  = __fadd_rn(__fadd_rn(p.x, fsx), -pix);
            const float dx2 = __fmul_rn(dx, dx);
            const float dy0 = __fadd_rn(p.y, -piy);
            const float dz0 = __fadd_rn(p.z, -piz);
            const float dy0s = __fmul_rn(dy0, dy0);
            const float dz0s = __fmul_rn(dz0, dz0);
            float dy1s = 0.0f, dz1s = 0.0f;
            if (hy) {
                const float dy1 = __fadd_rn(__fadd_rn(p.y, fy), -piy);
                dy1s = __fmul_rn(dy1, dy1);
            }
            if (hz) {
                const float dz1 = __fadd_rn(__fadd_rn(p.z, fz), -piz);
                dz1s = __fmul_rn(dz1, dz1);
            }
            {
                const float d2 = __fadd_rn(__fadd_rn(dx2, dy0s), dz0s);
                if (val && d2 <= CUT2 && !(selfchk && jorig == i))
                    atomicOr(&m00[jw], jb);
            }
            if (hy) {
                const float d2 = __fadd_rn(__fadd_rn(dx2, dy1s), dz0s);
                if (val && d2 <= CUT2) atomicOr(&mY[jw], jb);
                if (hz) {
                    const float d2b = __fadd_rn(__fadd_rn(dx2, dy1s), dz1s);
                    if (val && d2b <= CUT2) atomicOr(&mYZ[jw], jb);
                }
            }
            if (hz) {
                const float d2 = __fadd_rn(__fadd_rn(dx2, dy0s), dz1s);
                if (val && d2 <= CUT2) atomicOr(&mZ[jw], jb);
            }
        }
    }
    __syncthreads();

    // ---- Count: contiguous popc sweep over this warp's span ----
    const int myt0 = q * nA * 16;
    const int myt1 = myt0 + nA * 16;
    int cnt = 0;
    for (int t = myt0 + lane; t < myt1; t += 32) cnt += __popc(s_mask[t]);
#pragma unroll
    for (int d = 16; d; d >>= 1) cnt += __shfl_xor_sync(0xFFFFFFFFu, cnt, d);
    if (lane == 0) s_wcnt[q] = cnt;
    __syncthreads();

    int base = 0, rowTotal = 0;
#pragma unroll
    for (int q2 = 0; q2 < WARPS_PER_ROW; q2++) {
        const int cc = s_wcnt[q2];
        if (q2 < q) base += cc;
        rowTotal += cc;
    }

    // ---- Emit phase 1: ordered bit expansion -> 16-bit codes in smem ----
    {
        int off = base;
        int slot = 0;
        for (int zi = 0; zi < 3; zi++) {
            if ((zi == 0 && !okzm) || (zi == 2 && !okzp)) continue;
            for (int yi = 0; yi < 3; yi++) {
                if ((yi == 0 && !okym) || (yi == 2 && !okyp)) continue;
                for (int xi = 0; xi < 3; xi++) {
                    if ((xi == 0 && !okxm) || (xi == 2 && !okxp)) continue;
                    const int c = zi * 9 + yi * 3 + xi;     // canonical cell id
                    const int ccode = c << 11;
                    const int tb = slot << 6;
                    const int lo = myt0 > tb ? myt0 : tb;
                    const int hi = myt1 < tb + 64 ? myt1 : tb + 64;
                    for (int tg = lo; tg < hi; tg += 32) {
                        const int t = tg + lane;
                        unsigned word = (t < hi) ? s_mask[t] : 0u;
                        const int pc = __popc(word);
                        int ex = pc;
#pragma unroll
                        for (int d = 1; d < 32; d <<= 1) {
                            const int tt = __shfl_up_sync(0xFFFFFFFFu, ex, d);
                            if (lane >= d) ex += tt;
                        }
                        int myoff = off + ex - pc;
                        const int jbase = (t - tb) << 5;
                        while (word) {
                            const int bit = __ffs(word) - 1;
                            word &= word - 1;
                            if (myoff < KCAP)
                                s_stage[myoff] = (unsigned short)(ccode | (jbase + bit));
                            myoff++;
                        }
                        off += __shfl_sync(0xFFFFFFFFu, ex, 31);
                    }
                    slot++;
                }
            }
        }
    }
    __syncthreads();

    // ---- Emit phase 2: coalesced decode + fused tail fill ----
    float* __restrict__ out_neigh = out + (size_t)i * KCAP;
    float* __restrict__ out_cells = out + (size_t)NPTS * KCAP + (size_t)i * KCAP * 3;
    const int filled = (rowTotal < KCAP) ? rowTotal : KCAP;
    for (int e = tid; e < KCAP; e += NTHREADS) {
        float vn, c0, c1, c2;
        if (e < filled) {
            const int code = s_stage[e];
            const int j = code & 2047;
            const int c = code >> 11;
            vn = (float)j;
            c0 = (float)(c % 3 - 1);
            c1 = (float)((c / 3) % 3 - 1);
            c2 = (float)(c / 9 - 1);
        } else {
            vn = -1.0f; c0 = 1.0f; c1 = 1.0f; c2 = 1.0f;
        }
        out_neigh[e]         = vn;
        out_cells[3 * e]     = c0;
        out_cells[3 * e + 1] = c1;
        out_cells[3 * e + 2] = c2;
    }
    if (tid == 0) {
        atomicMax((int*)(out + MAX_OFFSET), __float_as_int((float)rowTotal));
    }
}

extern "C" void kernel_launch(void* const* d_in, const int* in_sizes, int n_in,
                              void* d_out, int out_size) {
    const float* pos = (const float*)d_in[0];
    float* out = (float*)d_out;
    pb_sort_kernel<<<1, 1024>>>(pos, out + MAX_OFFSET);
    pb_nbr_kernel<<<NPTS, NTHREADS>>>(pos, out);
}

// round 15
// speedup vs baseline: 1.0501x; 1.0398x over previous
#include <cuda_runtime.h>

#define NPTS 2048
#define KCAP 256
#define NTHREADS 256
#define ROWS_PER_BLOCK 2
#define WARPS_PER_ROW 4
#define CUT2 0.09f
#define EPSB 1e-3f
#define MWORDS 512    // 8 active-slot cells max * 64 words

#define MAX_OFFSET ((size_t)NPTS * KCAP * 4)

// Scratch (__device__ globals, allocation-free)
__device__ float4 g_sorted[NPTS];   // x-bucket-sorted points; .w = original j (bits)
__device__ int    g_bstart[257];    // bucket start offsets

// Single-block counting sort by x-bucket, 1024 threads (2 pts each).
__global__ __launch_bounds__(1024)
void pb_sort_kernel(const float* __restrict__ pos, float* __restrict__ out_max) {
    __shared__ int hist[256];
    __shared__ int cursor[256];
    __shared__ int wsum[8];
    const int tid = threadIdx.x;
    if (tid < 256) hist[tid] = 0;
    __syncthreads();

    float4 p[2]; int b[2];
#pragma unroll
    for (int rr = 0; rr < 2; rr++) {
        const int j = tid + rr * 1024;
        const float xx = pos[3 * j], yy = pos[3 * j + 1], zz = pos[3 * j + 2];
        int bb = (int)(xx * 256.0f);
        bb = bb < 0 ? 0 : (bb > 255 ? 255 : bb);
        p[rr] = make_float4(xx, yy, zz, __int_as_float(j));
        b[rr] = bb;
        atomicAdd(&hist[bb], 1);
    }
    __syncthreads();

    int incl = 0, v = 0;
    if (tid < 256) {
        const int lane = tid & 31;
        v = hist[tid];
        incl = v;
#pragma unroll
        for (int d = 1; d < 32; d <<= 1) {
            const int t = __shfl_up_sync(0xFFFFFFFFu, incl, d);
            if (lane >= d) incl += t;
        }
        if (lane == 31) wsum[tid >> 5] = incl;
    }
    __syncthreads();
    if (tid < 256) {
        const int w = tid >> 5;
        int woff = 0;
        for (int k = 0; k < w; k++) woff += wsum[k];
        const int excl = woff + incl - v;
        cursor[tid] = excl;
        g_bstart[tid] = excl;
        if (tid == 0) { g_bstart[256] = NPTS; *out_max = 0.0f; }
    }
    __syncthreads();

#pragma unroll
    for (int rr = 0; rr < 2; rr++) {
        const int dst = atomicAdd(&cursor[b[rr]], 1);
        g_sorted[dst] = p[rr];
    }
}

__global__ __launch_bounds__(NTHREADS, 7)
void pb_nbr_kernel(const float* __restrict__ pos, float* __restrict__ out) {
    __shared__ unsigned s_mask[ROWS_PER_BLOCK][MWORDS];           // 4 KB
    __shared__ unsigned short s_stage[ROWS_PER_BLOCK][KCAP];      // 1 KB
    __shared__ int s_wcnt[ROWS_PER_BLOCK][WARPS_PER_ROW];

    const int tid  = threadIdx.x;
    const int lane = tid & 31;
    const int w    = tid >> 5;
    const int r    = w >> 2;
    const int q    = w & 3;

    const int i = blockIdx.x * ROWS_PER_BLOCK + r;
    const float pix = __ldg(&pos[3 * i]);
    const float piy = __ldg(&pos[3 * i + 1]);
    const float piz = __ldg(&pos[3 * i + 2]);

    // Per-dim shift feasibility (margin 1e-4 >> fp32 rounding); -1/+1 mutually exclusive.
    const bool okxm = pix < 0.30001f, okxp = pix > 0.69999f;
    const bool okym = piy < 0.30001f, okyp = piy > 0.69999f;
    const bool okzm = piz < 0.30001f, okzp = piz > 0.69999f;

    const int nx = 1 + okxm + okxp, ny = 1 + okym + okyp, nz = 1 + okzm + okzp;
    const int nA = nx * ny * nz;
    const bool hy = okym || okyp;
    const bool hz = okzm || okzp;
    const float fy = okym ? -1.0f : 1.0f;
    const float fz = okzm ? -1.0f : 1.0f;

    // Zero only this row's active words (the row's 4 warps cover nA*64 words)
    {
        unsigned* __restrict__ rm = s_mask[r];
        const int rowTid128 = tid & 127;
        for (int k = rowTid128; k < nA * 64; k += 128) rm[k] = 0u;
    }
    __syncthreads();

    // Ranks within ascending active lists -> slot = (posz*ny+posy)*nx+posx.
    const int posx1 = okxm ? 1 : 0;
    const int posy1 = okym ? 1 : 0;
    const int posz1 = okzm ? 1 : 0;
    const int posyS = okym ? 0 : 1;
    const int poszS = okzm ? 0 : 1;
    const int base00 = (posz1 * ny + posy1) * nx;
    const int baseY  = (posz1 * ny + posyS) * nx;
    const int baseZ  = (poszS * ny + posy1) * nx;
    const int baseYZ = (poszS * ny + posyS) * nx;

    // x bucket windows (conservative supersets)
    int blo0 = (int)floorf((pix - 0.3f - EPSB) * 256.0f); if (blo0 < 0) blo0 = 0;
    int bhi0 = (int)floorf((pix + 0.3f + EPSB) * 256.0f); if (bhi0 > 255) bhi0 = 255;
    int blo1 = (int)floorf((pix + 0.7f - EPSB) * 256.0f);
    if (blo1 > 255) blo1 = 255; if (blo1 < 0) blo1 = 0;
    int bhi2 = (int)floorf((pix - 0.7f + EPSB) * 256.0f);
    if (bhi2 > 255) bhi2 = 255; if (bhi2 < 0) bhi2 = 0;

    unsigned* __restrict__ rmask = s_mask[r];

    // ---- Discovery: order-free; hits -> flat slot bitmask via atomicOr ----
#pragma unroll
    for (int s = 0; s < 3; s++) {
        bool sval; float fsx; int posx, kb0, kb1; bool selfchk;
        if (s == 0)      { sval = true; fsx =  0.0f; posx = posx1;  kb0 = blo0; kb1 = bhi0; selfchk = true;  }
        else if (s == 1) { sval = okxm; fsx = -1.0f; posx = 0;      kb0 = blo1; kb1 = 255;  selfchk = false; }
        else             { sval = okxp; fsx =  1.0f; posx = nx - 1; kb0 = 0;    kb1 = bhi2; selfchk = false; }
        if (!sval) continue;
        unsigned* __restrict__ m00 = rmask + ((base00 + posx) << 6);
        unsigned* __restrict__ mY  = rmask + ((baseY  + posx) << 6);
        unsigned* __restrict__ mZ  = rmask + ((baseZ  + posx) << 6);
        unsigned* __restrict__ mYZ = rmask + ((baseYZ + posx) << 6);
        const int k0 = __ldg(&g_bstart[kb0]);
        const int k1 = __ldg(&g_bstart[kb1 + 1]);

        for (int base = k0 + q * 32; base < k1; base += WARPS_PER_ROW * 32) {
            const int k = base + lane;
            const bool val = (k < k1);
            const float4 p = __ldg(&g_sorted[val ? k : k0]);
            const int jorig = __float_as_int(p.w);
            const int jw = jorig >> 5;
            const unsigned jb = 1u << (jorig & 31);
            // Exact reference rounding: ((p_j + s) - p_i), plain mul/add, no FMA.
            const float dx  = __fadd_rn(__fadd_rn(p.x, fsx), -pix);
            const float dx2 = __fmul_rn(dx, dx);
            const float dy0 = __fadd_rn(p.y, -piy);
            const float dz0 = __fadd_rn(p.z, -piz);
            const float dy0s = __fmul_rn(dy0, dy0);
            const float dz0s = __fmul_rn(dz0, dz0);
            float dy1s = 0.0f, dz1s = 0.0f;
            if (hy) {
                const float dy1 = __fadd_rn(__fadd_rn(p.y, fy), -piy);
                dy1s = __fmul_rn(dy1, dy1);
            }
            if (hz) {
                const float dz1 = __fadd_rn(__fadd_rn(p.z, fz), -piz);
                dz1s = __fmul_rn(dz1, dz1);
            }
            {
                const float d2 = __fadd_rn(__fadd_rn(dx2, dy0s), dz0s);
                if (val && d2 <= CUT2 && !(selfchk && jorig == i))
                    atomicOr(&m00[jw], jb);
            }
            if (hy) {
                const float d2 = __fadd_rn(__fadd_rn(dx2, dy1s), dz0s);
                if (val && d2 <= CUT2) atomicOr(&mY[jw], jb);
                if (hz) {
                    const float d2b = __fadd_rn(__fadd_rn(dx2, dy1s), dz1s);
                    if (val && d2b <= CUT2) atomicOr(&mYZ[jw], jb);
                }
            }
            if (hz) {
                const float d2 = __fadd_rn(__fadd_rn(dx2, dy0s), dz1s);
                if (val && d2 <= CUT2) atomicOr(&mZ[jw], jb);
            }
        }
    }
    __syncthreads();

    // ---- Count: contiguous popc sweep over this warp's span ----
    const int myt0 = q * nA * 16;
    const int myt1 = myt0 + nA * 16;
    int cnt = 0;
    for (int t = myt0 + lane; t < myt1; t += 32) cnt += __popc(rmask[t]);
#pragma unroll
    for (int d = 16; d; d >>= 1) cnt += __shfl_xor_sync(0xFFFFFFFFu, cnt, d);
    if (lane == 0) s_wcnt[r][q] = cnt;
    __syncthreads();

    int base = 0, rowTotal = 0;
#pragma unroll
    for (int q2 = 0; q2 < WARPS_PER_ROW; q2++) {
        const int cc = s_wcnt[r][q2];
        if (q2 < q) base += cc;
        rowTotal += cc;
    }

    // ---- Emit phase 1: ordered bit expansion -> 16-bit codes in smem ----
    {
        unsigned short* __restrict__ rstage = s_stage[r];
        int off = base;
        int slot = 0;
        for (int zi = 0; zi < 3; zi++) {
            if ((zi == 0 && !okzm) || (zi == 2 && !okzp)) continue;
            for (int yi = 0; yi < 3; yi++) {
                if ((yi == 0 && !okym) || (yi == 2 && !okyp)) continue;
                for (int xi = 0; xi < 3; xi++) {
                    if ((xi == 0 && !okxm) || (xi == 2 && !okxp)) continue;
                    const int c = zi * 9 + yi * 3 + xi;     // canonical cell id
                    const int ccode = c << 11;
                    const int tb = slot << 6;
                    const int lo = myt0 > tb ? myt0 : tb;
                    const int hi = myt1 < tb + 64 ? myt1 : tb + 64;
                    for (int tg = lo; tg < hi; tg += 32) {
                        const int t = tg + lane;
                        unsigned word = (t < hi) ? rmask[t] : 0u;
                        const int pc = __popc(word);
                        int ex = pc;
#pragma unroll
                        for (int d = 1; d < 32; d <<= 1) {
                            const int tt = __shfl_up_sync(0xFFFFFFFFu, ex, d);
                            if (lane >= d) ex += tt;
                        }
                        int myoff = off + ex - pc;
                        const int jbase = (t - tb) << 5;
                        while (word) {
                            const int bit = __ffs(word) - 1;
                            word &= word - 1;
                            if (myoff < KCAP)
                                rstage[myoff] = (unsigned short)(ccode | (jbase + bit));
                            myoff++;
                        }
                        off += __shfl_sync(0xFFFFFFFFu, ex, 31);
                    }
                    slot++;
                }
            }
        }
    }
    __syncthreads();

    // ---- Emit phase 2: coalesced decode + fused tail fill ----
    float* __restrict__ out_neigh = out + (size_t)i * KCAP;
    float* __restrict__ out_cells = out + (size_t)NPTS * KCAP + (size_t)i * KCAP * 3;
    const unsigned short* __restrict__ rstage = s_stage[r];
    const int rowTid = tid & 127;
    const int filled = (rowTotal < KCAP) ? rowTotal : KCAP;
    for (int e = rowTid; e < KCAP; e += 128) {
        float vn, c0, c1, c2;
        if (e < filled) {
            const int code = rstage[e];
            const int j = code & 2047;
            const int c = code >> 11;
            vn = (float)j;
            c0 = (float)(c % 3 - 1);
            c1 = (float)((c / 3) % 3 - 1);
            c2 = (float)(c / 9 - 1);
        } else {
            vn = -1.0f; c0 = 1.0f; c1 = 1.0f; c2 = 1.0f;
        }
        out_neigh[e]         = vn;
        out_cells[3 * e]     = c0;
        out_cells[3 * e + 1] = c1;
        out_cells[3 * e + 2] = c2;
    }
    if (q == 0 && lane == 0) {
        atomicMax((int*)(out + MAX_OFFSET), __float_as_int((float)rowTotal));
    }
}

extern "C" void kernel_launch(void* const* d_in, const int* in_sizes, int n_in,
                              void* d_out, int out_size) {
    const float* pos = (const float*)d_in[0];
    float* out = (float*)d_out;
    pb_sort_kernel<<<1, 1024>>>(pos, out + MAX_OFFSET);
    pb_nbr_kernel<<<NPTS / ROWS_PER_BLOCK, NTHREADS>>>(pos, out);
}

// round 16
// speedup vs baseline: 1.1123x; 1.0593x over previous
#include <cuda_runtime.h>

#define NPTS 2048
#define KCAP 256
#define NTHREADS 256
#define ROWS_PER_BLOCK 2
#define WARPS_PER_ROW 4
#define CUT2 0.09f
#define EPSB 1e-3f
#define MWORDS 512    // 8 active-slot cells max * 64 words

#define MAX_OFFSET ((size_t)NPTS * KCAP * 4)

// Scratch (__device__ globals, allocation-free)
__device__ float4 g_sorted[NPTS];   // x-bucket-sorted points; .w = original j (bits)
__device__ int    g_bstart[257];    // bucket start offsets

// Single-block counting sort by x-bucket, 1024 threads (2 pts each).
__global__ __launch_bounds__(1024)
void pb_sort_kernel(const float* __restrict__ pos, float* __restrict__ out_max) {
    __shared__ int hist[256];
    __shared__ int cursor[256];
    __shared__ int wsum[8];
    const int tid = threadIdx.x;
    if (tid < 256) hist[tid] = 0;
    __syncthreads();

    float4 p[2]; int b[2];
#pragma unroll
    for (int rr = 0; rr < 2; rr++) {
        const int j = tid + rr * 1024;
        const float xx = pos[3 * j], yy = pos[3 * j + 1], zz = pos[3 * j + 2];
        int bb = (int)(xx * 256.0f);
        bb = bb < 0 ? 0 : (bb > 255 ? 255 : bb);
        p[rr] = make_float4(xx, yy, zz, __int_as_float(j));
        b[rr] = bb;
        atomicAdd(&hist[bb], 1);
    }
    __syncthreads();

    int incl = 0, v = 0;
    if (tid < 256) {
        const int lane = tid & 31;
        v = hist[tid];
        incl = v;
#pragma unroll
        for (int d = 1; d < 32; d <<= 1) {
            const int t = __shfl_up_sync(0xFFFFFFFFu, incl, d);
            if (lane >= d) incl += t;
        }
        if (lane == 31) wsum[tid >> 5] = incl;
    }
    __syncthreads();
    if (tid < 256) {
        const int w = tid >> 5;
        int woff = 0;
        for (int k = 0; k < w; k++) woff += wsum[k];
        const int excl = woff + incl - v;
        cursor[tid] = excl;
        g_bstart[tid] = excl;
        if (tid == 0) { g_bstart[256] = NPTS; *out_max = 0.0f; }
    }
    __syncthreads();

#pragma unroll
    for (int rr = 0; rr < 2; rr++) {
        const int dst = atomicAdd(&cursor[b[rr]], 1);
        g_sorted[dst] = p[rr];
    }
}

__global__ __launch_bounds__(NTHREADS, 7)
void pb_nbr_kernel(const float* __restrict__ pos, float* __restrict__ out) {
    __shared__ unsigned s_mask[ROWS_PER_BLOCK][MWORDS];           // 4 KB
    __shared__ unsigned short s_stage[ROWS_PER_BLOCK][KCAP];      // 1 KB
    __shared__ unsigned short s_ccode[ROWS_PER_BLOCK][8];
    __shared__ int s_wcnt[ROWS_PER_BLOCK][WARPS_PER_ROW];

    const int tid  = threadIdx.x;
    const int lane = tid & 31;
    const int w    = tid >> 5;
    const int r    = w >> 2;
    const int q    = w & 3;
    const unsigned lmask = (1u << lane) - 1u;

    const int i = blockIdx.x * ROWS_PER_BLOCK + r;
    const float pix = __ldg(&pos[3 * i]);
    const float piy = __ldg(&pos[3 * i + 1]);
    const float piz = __ldg(&pos[3 * i + 2]);

    // Per-dim shift feasibility (margin 1e-4 >> fp32 rounding); -1/+1 mutually exclusive.
    const bool okxm = pix < 0.30001f, okxp = pix > 0.69999f;
    const bool okym = piy < 0.30001f, okyp = piy > 0.69999f;
    const bool okzm = piz < 0.30001f, okzp = piz > 0.69999f;

    const int nx = 1 + okxm + okxp, ny = 1 + okym + okyp, nz = 1 + okzm + okzp;
    const int nA = nx * ny * nz;
    const bool hy = okym || okyp;
    const bool hz = okzm || okzp;
    const float fy = okym ? -1.0f : 1.0f;
    const float fz = okzm ? -1.0f : 1.0f;

    // slot -> canonical cell code table (slot order == ascending c; x fastest in both)
    if (q == 0) {
        bool act = false;
        if (lane < 27) {
            const int xi = lane % 3, yi = (lane / 3) % 3, zi = lane / 9;
            const bool ax = (xi == 1) || (xi == 0 && okxm) || (xi == 2 && okxp);
            const bool ay = (yi == 1) || (yi == 0 && okym) || (yi == 2 && okyp);
            const bool az = (zi == 1) || (zi == 0 && okzm) || (zi == 2 && okzp);
            act = ax && ay && az;
        }
        const unsigned b = __ballot_sync(0xFFFFFFFFu, act);
        if (act) s_ccode[r][__popc(b & lmask)] = (unsigned short)(lane << 11);
    }

    // Zero only this row's active words (the row's 4 warps cover nA*64 words)
    {
        unsigned* __restrict__ rm = s_mask[r];
        const int rowTid128 = tid & 127;
        for (int k = rowTid128; k < nA * 64; k += 128) rm[k] = 0u;
    }
    __syncthreads();

    // Ranks within ascending active lists -> slot = (posz*ny+posy)*nx+posx.
    const int posx1 = okxm ? 1 : 0;
    const int posy1 = okym ? 1 : 0;
    const int posz1 = okzm ? 1 : 0;
    const int posyS = okym ? 0 : 1;
    const int poszS = okzm ? 0 : 1;
    const int base00 = (posz1 * ny + posy1) * nx;
    const int baseY  = (posz1 * ny + posyS) * nx;
    const int baseZ  = (poszS * ny + posy1) * nx;
    const int baseYZ = (poszS * ny + posyS) * nx;

    // x bucket windows (conservative supersets)
    int blo0 = (int)floorf((pix - 0.3f - EPSB) * 256.0f); if (blo0 < 0) blo0 = 0;
    int bhi0 = (int)floorf((pix + 0.3f + EPSB) * 256.0f); if (bhi0 > 255) bhi0 = 255;
    int blo1 = (int)floorf((pix + 0.7f - EPSB) * 256.0f);
    if (blo1 > 255) blo1 = 255; if (blo1 < 0) blo1 = 0;
    int bhi2 = (int)floorf((pix - 0.7f + EPSB) * 256.0f);
    if (bhi2 > 255) bhi2 = 255; if (bhi2 < 0) bhi2 = 0;

    unsigned* __restrict__ rmask = s_mask[r];

    // ---- Discovery: order-free; hits -> flat slot bitmask via atomicOr ----
#pragma unroll
    for (int s = 0; s < 3; s++) {
        bool sval; float fsx; int posx, kb0, kb1; bool selfchk;
        if (s == 0)      { sval = true; fsx =  0.0f; posx = posx1;  kb0 = blo0; kb1 = bhi0; selfchk = true;  }
        else if (s == 1) { sval = okxm; fsx = -1.0f; posx = 0;      kb0 = blo1; kb1 = 255;  selfchk = false; }
        else             { sval = okxp; fsx =  1.0f; posx = nx - 1; kb0 = 0;    kb1 = bhi2; selfchk = false; }
        if (!sval) continue;
        unsigned* __restrict__ m00 = rmask + ((base00 + posx) << 6);
        unsigned* __restrict__ mY  = rmask + ((baseY  + posx) << 6);
        unsigned* __restrict__ mZ  = rmask + ((baseZ  + posx) << 6);
        unsigned* __restrict__ mYZ = rmask + ((baseYZ + posx) << 6);
        const int k0 = __ldg(&g_bstart[kb0]);
        const int k1 = __ldg(&g_bstart[kb1 + 1]);

        for (int base = k0 + q * 32; base < k1; base += WARPS_PER_ROW * 32) {
            const int k = base + lane;
            const bool val = (k < k1);
            const float4 p = __ldg(&g_sorted[val ? k : k0]);
            const int jorig = __float_as_int(p.w);
            const int jw = jorig >> 5;
            const unsigned jb = 1u << (jorig & 31);
            // Exact reference rounding: ((p_j + s) - p_i), plain mul/add, no FMA.
            const float dx  = __fadd_rn(__fadd_rn(p.x, fsx), -pix);
            const float dx2 = __fmul_rn(dx, dx);
            const float dy0 = __fadd_rn(p.y, -piy);
            const float dz0 = __fadd_rn(p.z, -piz);
            const float dy0s = __fmul_rn(dy0, dy0);
            const float dz0s = __fmul_rn(dz0, dz0);
            float dy1s = 0.0f, dz1s = 0.0f;
            if (hy) {
                const float dy1 = __fadd_rn(__fadd_rn(p.y, fy), -piy);
                dy1s = __fmul_rn(dy1, dy1);
            }
            if (hz) {
                const float dz1 = __fadd_rn(__fadd_rn(p.z, fz), -piz);
                dz1s = __fmul_rn(dz1, dz1);
            }
            {
                const float d2 = __fadd_rn(__fadd_rn(dx2, dy0s), dz0s);
                if (val && d2 <= CUT2 && !(selfchk && jorig == i))
                    atomicOr(&m00[jw], jb);
            }
            if (hy) {
                const float d2 = __fadd_rn(__fadd_rn(dx2, dy1s), dz0s);
                if (val && d2 <= CUT2) atomicOr(&mY[jw], jb);
                if (hz) {
                    const float d2b = __fadd_rn(__fadd_rn(dx2, dy1s), dz1s);
                    if (val && d2b <= CUT2) atomicOr(&mYZ[jw], jb);
                }
            }
            if (hz) {
                const float d2 = __fadd_rn(__fadd_rn(dx2, dy0s), dz1s);
                if (val && d2 <= CUT2) atomicOr(&mZ[jw], jb);
            }
        }
    }
    __syncthreads();

    // ---- Count: contiguous popc sweep over this warp's span ----
    const int myt0 = q * nA * 16;
    const int myt1 = myt0 + nA * 16;
    int cnt = 0;
    for (int t = myt0 + lane; t < myt1; t += 32) cnt += __popc(rmask[t]);
#pragma unroll
    for (int d = 16; d; d >>= 1) cnt += __shfl_xor_sync(0xFFFFFFFFu, cnt, d);
    if (lane == 0) s_wcnt[r][q] = cnt;
    __syncthreads();

    int base = 0, rowTotal = 0;
#pragma unroll
    for (int q2 = 0; q2 < WARPS_PER_ROW; q2++) {
        const int cc = s_wcnt[r][q2];
        if (q2 < q) base += cc;
        rowTotal += cc;
    }

    // ---- Emit phase 1: flat ordered bit expansion -> 16-bit codes in smem ----
    {
        unsigned short* __restrict__ rstage = s_stage[r];
        const unsigned short* __restrict__ ctab = s_ccode[r];
        int off = base;
        for (int tg = myt0; tg < myt1; tg += 32) {
            const int t = tg + lane;
            const bool tv = (t < myt1);
            unsigned word = tv ? rmask[t] : 0u;
            const int ccode = tv ? (int)ctab[t >> 6] : 0;
            const int jbase = (t & 63) << 5;
            const int pc = __popc(word);
            int ex = pc;
#pragma unroll
            for (int d = 1; d < 32; d <<= 1) {
                const int tt = __shfl_up_sync(0xFFFFFFFFu, ex, d);
                if (lane >= d) ex += tt;
            }
            int myoff = off + ex - pc;
            while (word) {
                const int bit = __ffs(word) - 1;
                word &= word - 1;
                if (myoff < KCAP)
                    rstage[myoff] = (unsigned short)(ccode | (jbase + bit));
                myoff++;
            }
            off += __shfl_sync(0xFFFFFFFFu, ex, 31);
        }
    }
    __syncthreads();

    // ---- Emit phase 2: coalesced decode + fused tail fill ----
    float* __restrict__ out_neigh = out + (size_t)i * KCAP;
    float* __restrict__ out_cells = out + (size_t)NPTS * KCAP + (size_t)i * KCAP * 3;
    const unsigned short* __restrict__ rstage = s_stage[r];
    const int rowTid = tid & 127;
    const int filled = (rowTotal < KCAP) ? rowTotal : KCAP;
    for (int e = rowTid; e < KCAP; e += 128) {
        float vn, c0, c1, c2;
        if (e < filled) {
            const int code = rstage[e];
            const int j = code & 2047;
            const int c = code >> 11;
            vn = (float)j;
            c0 = (float)(c % 3 - 1);
            c1 = (float)((c / 3) % 3 - 1);
            c2 = (float)(c / 9 - 1);
        } else {
            vn = -1.0f; c0 = 1.0f; c1 = 1.0f; c2 = 1.0f;
        }
        out_neigh[e]         = vn;
        out_cells[3 * e]     = c0;
        out_cells[3 * e + 1] = c1;
        out_cells[3 * e + 2] = c2;
    }
    if (q == 0 && lane == 0) {
        atomicMax((int*)(out + MAX_OFFSET), __float_as_int((float)rowTotal));
    }
}

extern "C" void kernel_launch(void* const* d_in, const int* in_sizes, int n_in,
                              void* d_out, int out_size) {
    const float* pos = (const float*)d_in[0];
    float* out = (float*)d_out;
    pb_sort_kernel<<<1, 1024>>>(pos, out + MAX_OFFSET);
    pb_nbr_kernel<<<NPTS / ROWS_PER_BLOCK, NTHREADS>>>(pos, out);
}